// round 9
// baseline (speedup 1.0000x reference)
#include <cuda_runtime.h>
#include <cstdint>

#define HIDDEN   2048
#define INTER    1408
#define GU_ROWS  (2 * INTER)   // 2816
#define TOPK     6
#define NEXPERTS 60

// Scratch (allocation-free rule: __device__ globals)
__device__ __align__(16) float g_inter[TOPK * INTER];   // silu(gate)*up

// topk_idx may be int32 or int64 depending on JAX x64 config.
// int64 little-endian pattern over first 6 words: [v0,0,v1,0,v2,0], v<60.
__device__ __forceinline__ int load_expert_idx(const void* p, int k) {
    const int* w = (const int*)p;
    bool is64 = (w[1] == 0) & (w[3] == 0) & (w[5] == 0) &
                ((unsigned)w[0] < (unsigned)NEXPERTS) &
                ((unsigned)w[2] < (unsigned)NEXPERTS) &
                ((unsigned)w[4] < (unsigned)NEXPERTS);
    if (is64) return (int)((const long long*)p)[k];
    return w[k];
}

__device__ __forceinline__ float dot4(float4 a, float4 b) {
    return a.x * b.x + a.y * b.y + a.z * b.z + a.w * b.w;
}

// ---------------------------------------------------------------------------
// Phase 1 (fused): one warp computes gate row i AND up row i of expert k,
// applies SiLU, writes inter directly. 32 weight float4s in flight per warp.
// ---------------------------------------------------------------------------
__global__ __launch_bounds__(256) void gu_silu_kernel(
    const float* __restrict__ x,
    const void*  __restrict__ idx,
    const float* __restrict__ gu)
{
    int warp = (blockIdx.x * blockDim.x + threadIdx.x) >> 5;
    int lane = threadIdx.x & 31;
    if (warp >= TOPK * INTER) return;

    int k = warp / INTER;
    int i = warp - k * INTER;
    int e = load_expert_idx(idx, k);

    const float4* __restrict__ grow =
        (const float4*)(gu + ((size_t)e * GU_ROWS + i) * HIDDEN);
    const float4* __restrict__ urow =
        (const float4*)(gu + ((size_t)e * GU_ROWS + INTER + i) * HIDDEN);
    const float4* __restrict__ xv = (const float4*)x;

    float accg = 0.f, accu = 0.f;
#pragma unroll
    for (int t = 0; t < HIDDEN / 4 / 32; t++) {   // 16 iters, fully unrolled
        float4 a = __ldcs(&grow[lane + 32 * t]);  // streaming: read-once weights
        float4 b = __ldcs(&urow[lane + 32 * t]);
        float4 v = xv[lane + 32 * t];             // L1-hot (8 KB vector)
        accg += dot4(a, v);
        accu += dot4(b, v);
    }
#pragma unroll
    for (int s = 16; s; s >>= 1) {
        accg += __shfl_xor_sync(0xFFFFFFFFu, accg, s);
        accu += __shfl_xor_sync(0xFFFFFFFFu, accu, s);
    }

    if (lane == 0) {
        float sig = 1.f / (1.f + __expf(-accg));
        g_inter[warp] = accg * sig * accu;
    }
}

// ---------------------------------------------------------------------------
// Phase 2: out[h] = sum_k w_k * dot(down_all[e_k][h][:], inter[k][:])
// block = 2 h values, 6 warps (one per expert, 2 rows each -> 22 loads
// in flight per warp). Deterministic smem reduce.
// ---------------------------------------------------------------------------
__global__ __launch_bounds__(TOPK * 32) void down_gemv_kernel(
    const void*  __restrict__ idx,
    const float* __restrict__ wts,
    const float* __restrict__ down,
    float*       __restrict__ out)
{
    int h0   = blockIdx.x * 2;
    int k    = threadIdx.x >> 5;
    int lane = threadIdx.x & 31;
    int e    = load_expert_idx(idx, k);

    const float4* __restrict__ row0 =
        (const float4*)(down + ((size_t)e * HIDDEN + h0) * INTER);
    const float4* __restrict__ row1 =
        (const float4*)(down + ((size_t)e * HIDDEN + h0 + 1) * INTER);
    const float4* __restrict__ iv = (const float4*)(g_inter + k * INTER);

    float acc0 = 0.f, acc1 = 0.f;
#pragma unroll
    for (int t = 0; t < INTER / 4 / 32; t++) {    // 11 iters, fully unrolled
        float4 a0 = __ldcs(&row0[lane + 32 * t]);
        float4 a1 = __ldcs(&row1[lane + 32 * t]);
        float4 b  = iv[lane + 32 * t];            // L2/L1-resident (34 KB)
        acc0 += dot4(a0, b);
        acc1 += dot4(a1, b);
    }
#pragma unroll
    for (int s = 16; s; s >>= 1) {
        acc0 += __shfl_xor_sync(0xFFFFFFFFu, acc0, s);
        acc1 += __shfl_xor_sync(0xFFFFFFFFu, acc1, s);
    }

    __shared__ float part[TOPK][2];
    if (lane == 0) {
        float w = wts[k];
        part[k][0] = acc0 * w;
        part[k][1] = acc1 * w;
    }
    __syncthreads();

    if (threadIdx.x < 2) {
        float s = 0.f;
#pragma unroll
        for (int i = 0; i < TOPK; i++) s += part[i][threadIdx.x];
        out[h0 + threadIdx.x] = s;
    }
}

// ---------------------------------------------------------------------------
// Inputs (metadata order): x_bc1t[2048] f32, topk_idx[6] i32/i64,
// topk_weights[6] f32, gate_up_all[60*2816*2048] f32, down_all[60*2048*1408] f32
// Output: [2048] f32
// ---------------------------------------------------------------------------
extern "C" void kernel_launch(void* const* d_in, const int* in_sizes, int n_in,
                              void* d_out, int out_size)
{
    const float* x    = (const float*)d_in[0];
    const void*  idx  = d_in[1];
    const float* wts  = (const float*)d_in[2];
    const float* gu   = (const float*)d_in[3];
    const float* down = (const float*)d_in[4];
    float*       out  = (float*)d_out;

    const int p1_warps = TOPK * INTER;                       // 8448 warps
    gu_silu_kernel<<<(p1_warps * 32 + 255) / 256, 256>>>(x, idx, gu);

    down_gemv_kernel<<<HIDDEN / 2, TOPK * 32>>>(idx, wts, down, out);
}